// round 14
// baseline (speedup 1.0000x reference)
#include <cuda_runtime.h>
#include <cuda_fp16.h>
#include <cstdint>

#define BATCH 2
#define CCH 128
#define ICH 16
#define NP 9216
#define QB 64                // queries per CTA
#define KT 128               // keys per tile
#define NT (NP / KT)         // 72
#define NQB (NP / QB)        // 144
#define LOG2E 1.4426950408889634f

// smem: 3 buffers of (K: 128 keys x 32B = 4096) + (V: 32 rows x 272B = 8704)
#define BUF_STRIDE 12800
#define KOFF 0
#define VOFF 4096
#define WO_OFF 38400
#define BO_OFF 46592
#define SO_OFF 47104
#define SMEM_BYTES 51456
// cross-warp partials alias buffer region after mainloop: [64][18]

typedef unsigned int u32;

__device__ __align__(16) u32 g_q2[BATCH * NP * 16];            // per query: 8 fp16-hi pair words, 8 lo
__device__ __align__(16) u32 g_k2[BATCH * NP * 8];             // per key (fp16 single), tg-interleaved
__device__ __align__(16) unsigned short g_vt[BATCH * 32 * NP]; // rows 0-15 Vh (bf16), 16-31 Vl; keys pair-permuted per 16

static __device__ __forceinline__ float ex2f(float x) {
    float r; asm("ex2.approx.f32 %0, %1;" : "=f"(r) : "f"(x)); return r;
}
static __device__ __forceinline__ u32 pack_bf16_rn(float p0, float p1) {
    u32 d; asm("cvt.rn.satfinite.bf16x2.f32 %0, %1, %2;" : "=r"(d) : "f"(p1), "f"(p0)); return d;
}
static __device__ __forceinline__ float lo_of(float a) {
    return a - __uint_as_float(__float_as_uint(a) & 0xFFFF0000u);
}
static __device__ __forceinline__ u32 pack_f16(__half a, __half b) {
    return (u32)__half_as_ushort(a) | ((u32)__half_as_ushort(b) << 16);
}
static __device__ __forceinline__ void cpasync16(void* s, const void* g) {
    u32 a = (u32)__cvta_generic_to_shared(s);
    asm volatile("cp.async.cg.shared.global [%0], [%1], 16;" :: "r"(a), "l"(g));
}
#define CP_COMMIT() asm volatile("cp.async.commit_group;" ::: "memory")

#define MMA_F16(d, a, b0, b1) \
    asm volatile("mma.sync.aligned.m16n8k16.row.col.f32.f16.f16.f32 " \
        "{%0,%1,%2,%3},{%4,%5,%6,%7},{%8,%9},{%0,%1,%2,%3};" \
        : "+f"((d)[0]), "+f"((d)[1]), "+f"((d)[2]), "+f"((d)[3]) \
        : "r"((a)[0]), "r"((a)[1]), "r"((a)[2]), "r"((a)[3]), "r"(b0), "r"(b1))

#define MMA_BF16(d, a, b0, b1) \
    asm volatile("mma.sync.aligned.m16n8k16.row.col.f32.bf16.bf16.f32 " \
        "{%0,%1,%2,%3},{%4,%5,%6,%7},{%8,%9},{%0,%1,%2,%3};" \
        : "+f"((d)[0]), "+f"((d)[1]), "+f"((d)[2]), "+f"((d)[3]) \
        : "r"((a)[0]), "r"((a)[1]), "r"((a)[2]), "r"((a)[3]), "r"(b0), "r"(b1))

// ============================================================================
// Kernel 1: qkv projections -> fp16 hi/lo Q ; fp16 single K ; bf16 hi/lo V
// ============================================================================
__global__ void __launch_bounds__(256) qkv_kernel(
    const float* __restrict__ x,
    const float* __restrict__ Wq, const float* __restrict__ bq,
    const float* __restrict__ Wk, const float* __restrict__ bk,
    const float* __restrict__ Wv, const float* __restrict__ bv)
{
    __shared__ float sWq[ICH * CCH], sWk[ICH * CCH], sWv[ICH * CCH];
    __shared__ float sb[3 * ICH];
    for (int i = threadIdx.x; i < ICH * CCH; i += 256) {
        sWq[i] = Wq[i]; sWk[i] = Wk[i]; sWv[i] = Wv[i];
    }
    if (threadIdx.x < ICH)            sb[threadIdx.x] = bq[threadIdx.x];
    else if (threadIdx.x < 2 * ICH)   sb[threadIdx.x] = bk[threadIdx.x - ICH];
    else if (threadIdx.x < 3 * ICH)   sb[threadIdx.x] = bv[threadIdx.x - 2 * ICH];
    __syncthreads();

    int gid = blockIdx.x * 256 + threadIdx.x;
    int b = gid / NP, n = gid % NP;
    const float* xb = x + (size_t)b * CCH * NP + n;

    float aq[ICH], ak[ICH], av[ICH];
    #pragma unroll
    for (int i = 0; i < ICH; i++) { aq[i] = 0.f; ak[i] = 0.f; av[i] = 0.f; }

    for (int c = 0; c < CCH; c += 4) {
        float x0 = xb[(size_t)(c + 0) * NP];
        float x1 = xb[(size_t)(c + 1) * NP];
        float x2 = xb[(size_t)(c + 2) * NP];
        float x3 = xb[(size_t)(c + 3) * NP];
        #pragma unroll
        for (int i = 0; i < ICH; i++) {
            float4 wq = *(const float4*)&sWq[i * CCH + c];
            aq[i] = fmaf(wq.x, x0, fmaf(wq.y, x1, fmaf(wq.z, x2, fmaf(wq.w, x3, aq[i]))));
            float4 wk = *(const float4*)&sWk[i * CCH + c];
            ak[i] = fmaf(wk.x, x0, fmaf(wk.y, x1, fmaf(wk.z, x2, fmaf(wk.w, x3, ak[i]))));
            float4 wv = *(const float4*)&sWv[i * CCH + c];
            av[i] = fmaf(wv.x, x0, fmaf(wv.y, x1, fmaf(wv.z, x2, fmaf(wv.w, x3, av[i]))));
        }
    }

    float qf[ICH], kf[ICH];
    #pragma unroll
    for (int i = 0; i < ICH; i++) {
        qf[i] = (aq[i] + sb[i]) * LOG2E;
        kf[i] = ak[i] + sb[ICH + i];
    }
    u32 qhi[8], qlo[8], khi[8];
    #pragma unroll
    for (int j = 0; j < 8; j++) {
        __half qh0 = __float2half_rn(qf[2 * j]),     qh1 = __float2half_rn(qf[2 * j + 1]);
        float  qlo0 = qf[2 * j] - __half2float(qh0), qlo1 = qf[2 * j + 1] - __half2float(qh1);
        qhi[j] = pack_f16(qh0, qh1);
        qlo[j] = pack_f16(__float2half_rn(qlo0), __float2half_rn(qlo1));
        khi[j] = pack_f16(__float2half_rn(kf[2 * j]), __float2half_rn(kf[2 * j + 1]));
    }
    u32* qo = g_q2 + (size_t)gid * 16;
    u32* ko = g_k2 + (size_t)gid * 8;
    #pragma unroll
    for (int j = 0; j < 8; j++) { qo[j] = qhi[j]; qo[8 + j] = qlo[j]; }
    #pragma unroll
    for (int tg = 0; tg < 4; tg++) {
        ko[tg * 2 + 0] = khi[tg];
        ko[tg * 2 + 1] = khi[tg + 4];
    }
    // V: keys pair-permuted within each 16-group so (b0,b1) is contiguous (LDS.64)
    {
        int idx16 = n & 15;
        int p = idx16 >> 1, e = idx16 & 1;
        int pp = (p < 4) ? (2 * p) : (2 * (p - 4) + 1);
        int nperm = (n & ~15) | (pp * 2 + e);
        unsigned short* vt = g_vt + (size_t)b * 32 * NP + nperm;
        #pragma unroll
        for (int i = 0; i < ICH; i++) {
            float vv = av[i] + sb[2 * ICH + i];
            vt[(size_t)i * NP]        = (unsigned short)(__float_as_uint(vv) >> 16);
            vt[(size_t)(16 + i) * NP] = (unsigned short)(__float_as_uint(lo_of(vv)) >> 16);
        }
    }
}

// ---------------- tile loader (256 threads, KT=128) ----------------
static __device__ __forceinline__ void load_tile(const char* gk, const char* gv,
                                                 char* dst, int t, int tid) {
    const char* ksrc = gk + (size_t)t * KT * 32;   // contiguous 4 KB
    cpasync16(dst + KOFF + tid * 16, ksrc + tid * 16);
    #pragma unroll
    for (int r = 0; r < 2; r++) {
        int idx = r * 256 + tid;
        int row = idx >> 4, c = idx & 15;
        cpasync16(dst + VOFF + row * 272 + c * 16,
                  gv + (size_t)row * (NP * 2) + t * 256 + c * 16);
    }
    CP_COMMIT();
}

// ============================================================================
// Kernel 2: HMMA flash attention; 16q x 64k per warp, 3 CTAs/SM
// ============================================================================
__global__ void __launch_bounds__(256, 3) attn_kernel(
    const float* __restrict__ x, const float* __restrict__ Wo,
    const float* __restrict__ bo, const float* __restrict__ gamma,
    float* __restrict__ y)
{
    extern __shared__ char smc[];
    const int tid = threadIdx.x;
    const int w = tid >> 5, lane = tid & 31;
    const int wq = w & 3;            // query group (16 queries)
    const int wk = w >> 2;           // key half of each tile (64 keys)
    const int gr = lane >> 2, tg = lane & 3;
    const int b  = blockIdx.x / NQB;
    const int q0 = (blockIdx.x % NQB) * QB;

    float* sWo = (float*)(smc + WO_OFF);
    float* sbo = (float*)(smc + BO_OFF);
    float* sO  = (float*)(smc + SO_OFF);
    for (int i = tid; i < ICH * CCH; i += 256) sWo[i] = Wo[i];
    if (tid < CCH) sbo[tid] = bo[tid];

    // Q fragments for this warp's 16 queries (rows wq*16 + gr, +8)
    const u32* qp  = g_q2 + (size_t)(b * NP + q0 + wq * 16 + gr) * 16;
    const u32* qp8 = qp + 8 * 16;
    u32 qh[4], ql[4];
    qh[0] = qp[tg];     qh[1] = qp8[tg];     qh[2] = qp[tg + 4];  qh[3] = qp8[tg + 4];
    ql[0] = qp[8 + tg]; ql[1] = qp8[8 + tg]; ql[2] = qp[12 + tg]; ql[3] = qp8[12 + tg];

    const u32 one_b = (gr == 0) ? 0x3F803F80u : 0u;   // bf16 ones, col 0

    float oA[2][4] = {}, oC[2][4] = {};   // [cb][4]
    float oD[4] = {};                      // ones-column

    const char* gk = (const char*)(g_k2 + (size_t)b * NP * 8);
    const char* gv = (const char*)(g_vt + (size_t)b * 32 * NP);

    load_tile(gk, gv, smc + 0 * BUF_STRIDE, 0, tid);
    load_tile(gk, gv, smc + 1 * BUF_STRIDE, 1, tid);

    int bidx = 0;   // t % 3
    for (int t = 0; t < NT; t++) {
        if (t + 1 < NT) { asm volatile("cp.async.wait_group 1;" ::: "memory"); }
        else            { asm volatile("cp.async.wait_group 0;" ::: "memory"); }
        __syncthreads();
        if (t + 2 < NT) {
            int nb = bidx + 2; if (nb >= 3) nb -= 3;
            load_tile(gk, gv, smc + nb * BUF_STRIDE, t + 2, tid);
        }

        const char* kb = smc + bidx * BUF_STRIDE + KOFF;
        const char* vb = smc + bidx * BUF_STRIDE + VOFF;

        #pragma unroll
        for (int c2 = 0; c2 < 4; c2++) {
            const int ck = wk * 4 + c2;   // 16-key chunk (of 8 per tile)
            const char* ka = kb + (ck * 16 + gr) * 32 + tg * 8;
            uint2 kw0 = *(const uint2*)ka;
            uint2 kw1 = *(const uint2*)(ka + 8 * 32);
            uint2 vh[2], vl[2];
            #pragma unroll
            for (int cb = 0; cb < 2; cb++) {
                const char* va = vb + (cb * 8 + gr) * 272 + ck * 32 + tg * 8;
                vh[cb] = *(const uint2*)va;
                vl[cb] = *(const uint2*)(va + 16 * 272);
            }
            float sa0[4] = {0.f,0.f,0.f,0.f}, sb0[4] = {0.f,0.f,0.f,0.f};
            float sa1[4] = {0.f,0.f,0.f,0.f}, sb1[4] = {0.f,0.f,0.f,0.f};
            MMA_F16(sa0, qh, kw0.x, kw0.y);
            MMA_F16(sb0, ql, kw0.x, kw0.y);
            MMA_F16(sa1, qh, kw1.x, kw1.y);
            MMA_F16(sb1, ql, kw1.x, kw1.y);

            float p00 = ex2f(sa0[0] + sb0[0]), p01 = ex2f(sa0[1] + sb0[1]);
            float p02 = ex2f(sa0[2] + sb0[2]), p03 = ex2f(sa0[3] + sb0[3]);
            float p10 = ex2f(sa1[0] + sb1[0]), p11 = ex2f(sa1[1] + sb1[1]);
            float p12 = ex2f(sa1[2] + sb1[2]), p13 = ex2f(sa1[3] + sb1[3]);
            u32 pah[4];
            pah[0] = pack_bf16_rn(p00, p01); pah[1] = pack_bf16_rn(p02, p03);
            pah[2] = pack_bf16_rn(p10, p11); pah[3] = pack_bf16_rn(p12, p13);

            #pragma unroll
            for (int cb = 0; cb < 2; cb++) {
                MMA_BF16(oA[cb], pah, vh[cb].x, vh[cb].y);
                MMA_BF16(oC[cb], pah, vl[cb].x, vl[cb].y);
            }
            MMA_BF16(oD, pah, one_b, one_b);
        }
        if (++bidx == 3) bidx = 0;
    }

    float ro[2][4];
    #pragma unroll
    for (int cb = 0; cb < 2; cb++)
        #pragma unroll
        for (int i = 0; i < 4; i++)
            ro[cb][i] = oA[cb][i] + oC[cb][i];

    __syncthreads();   // tile buffers dead; alias partials
    float* part = (float*)smc;   // [64][18]
    const int qi0 = wq * 16 + gr, qi1 = qi0 + 8;
    if (wk == 1) {
        #pragma unroll
        for (int cb = 0; cb < 2; cb++) {
            int col = cb * 8 + tg * 2;
            part[qi0 * 18 + col]     = ro[cb][0];
            part[qi0 * 18 + col + 1] = ro[cb][1];
            part[qi1 * 18 + col]     = ro[cb][2];
            part[qi1 * 18 + col + 1] = ro[cb][3];
        }
        if (tg == 0) {
            part[qi0 * 18 + 16] = oD[0];
            part[qi1 * 18 + 16] = oD[2];
        }
    }
    __syncthreads();
    if (wk == 0) {
        float dnA = __shfl_sync(0xFFFFFFFFu, oD[0], lane & ~3) + part[qi0 * 18 + 16];
        float dnB = __shfl_sync(0xFFFFFFFFu, oD[2], lane & ~3) + part[qi1 * 18 + 16];
        float id0 = 1.0f / dnA, id1 = 1.0f / dnB;
        #pragma unroll
        for (int cb = 0; cb < 2; cb++) {
            int col = cb * 8 + tg * 2;
            sO[qi0 * 17 + col]     = (ro[cb][0] + part[qi0 * 18 + col])     * id0;
            sO[qi0 * 17 + col + 1] = (ro[cb][1] + part[qi0 * 18 + col + 1]) * id0;
            sO[qi1 * 17 + col]     = (ro[cb][2] + part[qi1 * 18 + col])     * id1;
            sO[qi1 * 17 + col + 1] = (ro[cb][3] + part[qi1 * 18 + col + 1]) * id1;
        }
    }
    __syncthreads();

    // epilogue: y = gamma * (Wo @ O + bo) + x
    const float gam = gamma[0];
    for (int idx = tid; idx < CCH * QB; idx += 256) {
        int c = idx >> 6, q = idx & 63;
        const float* wr = sWo + c * ICH;
        const float* ov = sO + q * 17;
        float acc = 0.f;
        #pragma unroll
        for (int i = 0; i < ICH; i++) acc = fmaf(wr[i], ov[i], acc);
        size_t gi = ((size_t)(b * CCH + c)) * NP + (q0 + q);
        y[gi] = gam * (acc + sbo[c]) + x[gi];
    }
}

extern "C" void kernel_launch(void* const* d_in, const int* in_sizes, int n_in,
                              void* d_out, int out_size) {
    const float* x     = (const float*)d_in[0];
    const float* Wq    = (const float*)d_in[1];
    const float* bq    = (const float*)d_in[2];
    const float* Wk    = (const float*)d_in[3];
    const float* bk    = (const float*)d_in[4];
    const float* Wv    = (const float*)d_in[5];
    const float* bv    = (const float*)d_in[6];
    const float* Wo    = (const float*)d_in[7];
    const float* bo    = (const float*)d_in[8];
    const float* gamma = (const float*)d_in[9];
    float* y = (float*)d_out;

    cudaFuncSetAttribute(attn_kernel, cudaFuncAttributeMaxDynamicSharedMemorySize, SMEM_BYTES);

    qkv_kernel<<<(BATCH * NP) / 256, 256>>>(x, Wq, bq, Wk, bk, Wv, bv);
    attn_kernel<<<BATCH * NQB, 256, SMEM_BYTES>>>(x, Wo, bo, gamma, y);
}

// round 15
// speedup vs baseline: 1.0322x; 1.0322x over previous
#include <cuda_runtime.h>
#include <cuda_fp16.h>
#include <cstdint>

#define BATCH 2
#define CCH 128
#define ICH 16
#define NP 9216
#define QB 64                // queries per CTA
#define KT 128               // keys per tile
#define NT (NP / KT)         // 72
#define NQB (NP / QB)        // 144
#define LOG2E 1.4426950408889634f
#define THREADS 512

// smem: 3 buffers of (K: 128 keys x 32B = 4096) + (V: 32 rows x 272B = 8704)
#define BUF_STRIDE 12800
#define KOFF 0
#define VOFF 4096
#define WO_OFF 38400
#define BO_OFF 46592
#define SO_OFF 47104
#define SMEM_BYTES 51456
// cross-warp partials alias buffer region after mainloop: 3 slots x [64][18]

typedef unsigned int u32;

__device__ __align__(16) u32 g_q2[BATCH * NP * 16];            // per query: 8 fp16-hi pair words, 8 lo
__device__ __align__(16) u32 g_k2[BATCH * NP * 8];             // per key (fp16 single), tg-interleaved
__device__ __align__(16) unsigned short g_vt[BATCH * 32 * NP]; // rows 0-15 Vh (bf16), 16-31 Vl; keys pair-permuted per 16

static __device__ __forceinline__ float ex2f(float x) {
    float r; asm("ex2.approx.f32 %0, %1;" : "=f"(r) : "f"(x)); return r;
}
static __device__ __forceinline__ u32 pack_bf16_rn(float p0, float p1) {
    u32 d; asm("cvt.rn.satfinite.bf16x2.f32 %0, %1, %2;" : "=r"(d) : "f"(p1), "f"(p0)); return d;
}
static __device__ __forceinline__ float lo_of(float a) {
    return a - __uint_as_float(__float_as_uint(a) & 0xFFFF0000u);
}
static __device__ __forceinline__ u32 pack_f16(__half a, __half b) {
    return (u32)__half_as_ushort(a) | ((u32)__half_as_ushort(b) << 16);
}
static __device__ __forceinline__ void cpasync16(void* s, const void* g) {
    u32 a = (u32)__cvta_generic_to_shared(s);
    asm volatile("cp.async.cg.shared.global [%0], [%1], 16;" :: "r"(a), "l"(g));
}
#define CP_COMMIT() asm volatile("cp.async.commit_group;" ::: "memory")

#define MMA_F16(d, a, b0, b1) \
    asm volatile("mma.sync.aligned.m16n8k16.row.col.f32.f16.f16.f32 " \
        "{%0,%1,%2,%3},{%4,%5,%6,%7},{%8,%9},{%0,%1,%2,%3};" \
        : "+f"((d)[0]), "+f"((d)[1]), "+f"((d)[2]), "+f"((d)[3]) \
        : "r"((a)[0]), "r"((a)[1]), "r"((a)[2]), "r"((a)[3]), "r"(b0), "r"(b1))

#define MMA_BF16(d, a, b0, b1) \
    asm volatile("mma.sync.aligned.m16n8k16.row.col.f32.bf16.bf16.f32 " \
        "{%0,%1,%2,%3},{%4,%5,%6,%7},{%8,%9},{%0,%1,%2,%3};" \
        : "+f"((d)[0]), "+f"((d)[1]), "+f"((d)[2]), "+f"((d)[3]) \
        : "r"((a)[0]), "r"((a)[1]), "r"((a)[2]), "r"((a)[3]), "r"(b0), "r"(b1))

// ============================================================================
// Kernel 1: qkv projections -> fp16 hi/lo Q ; fp16 single K ; bf16 hi/lo V
// ============================================================================
__global__ void __launch_bounds__(256) qkv_kernel(
    const float* __restrict__ x,
    const float* __restrict__ Wq, const float* __restrict__ bq,
    const float* __restrict__ Wk, const float* __restrict__ bk,
    const float* __restrict__ Wv, const float* __restrict__ bv)
{
    __shared__ float sWq[ICH * CCH], sWk[ICH * CCH], sWv[ICH * CCH];
    __shared__ float sb[3 * ICH];
    for (int i = threadIdx.x; i < ICH * CCH; i += 256) {
        sWq[i] = Wq[i]; sWk[i] = Wk[i]; sWv[i] = Wv[i];
    }
    if (threadIdx.x < ICH)            sb[threadIdx.x] = bq[threadIdx.x];
    else if (threadIdx.x < 2 * ICH)   sb[threadIdx.x] = bk[threadIdx.x - ICH];
    else if (threadIdx.x < 3 * ICH)   sb[threadIdx.x] = bv[threadIdx.x - 2 * ICH];
    __syncthreads();

    int gid = blockIdx.x * 256 + threadIdx.x;
    int b = gid / NP, n = gid % NP;
    const float* xb = x + (size_t)b * CCH * NP + n;

    float aq[ICH], ak[ICH], av[ICH];
    #pragma unroll
    for (int i = 0; i < ICH; i++) { aq[i] = 0.f; ak[i] = 0.f; av[i] = 0.f; }

    for (int c = 0; c < CCH; c += 4) {
        float x0 = xb[(size_t)(c + 0) * NP];
        float x1 = xb[(size_t)(c + 1) * NP];
        float x2 = xb[(size_t)(c + 2) * NP];
        float x3 = xb[(size_t)(c + 3) * NP];
        #pragma unroll
        for (int i = 0; i < ICH; i++) {
            float4 wq = *(const float4*)&sWq[i * CCH + c];
            aq[i] = fmaf(wq.x, x0, fmaf(wq.y, x1, fmaf(wq.z, x2, fmaf(wq.w, x3, aq[i]))));
            float4 wk = *(const float4*)&sWk[i * CCH + c];
            ak[i] = fmaf(wk.x, x0, fmaf(wk.y, x1, fmaf(wk.z, x2, fmaf(wk.w, x3, ak[i]))));
            float4 wv = *(const float4*)&sWv[i * CCH + c];
            av[i] = fmaf(wv.x, x0, fmaf(wv.y, x1, fmaf(wv.z, x2, fmaf(wv.w, x3, av[i]))));
        }
    }

    float qf[ICH], kf[ICH];
    #pragma unroll
    for (int i = 0; i < ICH; i++) {
        qf[i] = (aq[i] + sb[i]) * LOG2E;
        kf[i] = ak[i] + sb[ICH + i];
    }
    u32 qhi[8], qlo[8], khi[8];
    #pragma unroll
    for (int j = 0; j < 8; j++) {
        __half qh0 = __float2half_rn(qf[2 * j]),     qh1 = __float2half_rn(qf[2 * j + 1]);
        float  qlo0 = qf[2 * j] - __half2float(qh0), qlo1 = qf[2 * j + 1] - __half2float(qh1);
        qhi[j] = pack_f16(qh0, qh1);
        qlo[j] = pack_f16(__float2half_rn(qlo0), __float2half_rn(qlo1));
        khi[j] = pack_f16(__float2half_rn(kf[2 * j]), __float2half_rn(kf[2 * j + 1]));
    }
    u32* qo = g_q2 + (size_t)gid * 16;
    u32* ko = g_k2 + (size_t)gid * 8;
    #pragma unroll
    for (int j = 0; j < 8; j++) { qo[j] = qhi[j]; qo[8 + j] = qlo[j]; }
    #pragma unroll
    for (int tg = 0; tg < 4; tg++) {
        ko[tg * 2 + 0] = khi[tg];
        ko[tg * 2 + 1] = khi[tg + 4];
    }
    // V: keys pair-permuted within each 16-group so (b0,b1) is contiguous (LDS.64)
    {
        int idx16 = n & 15;
        int p = idx16 >> 1, e = idx16 & 1;
        int pp = (p < 4) ? (2 * p) : (2 * (p - 4) + 1);
        int nperm = (n & ~15) | (pp * 2 + e);
        unsigned short* vt = g_vt + (size_t)b * 32 * NP + nperm;
        #pragma unroll
        for (int i = 0; i < ICH; i++) {
            float vv = av[i] + sb[2 * ICH + i];
            vt[(size_t)i * NP]        = (unsigned short)(__float_as_uint(vv) >> 16);
            vt[(size_t)(16 + i) * NP] = (unsigned short)(__float_as_uint(lo_of(vv)) >> 16);
        }
    }
}

// ---------------- tile loader (512 threads, KT=128) ----------------
static __device__ __forceinline__ void load_tile(const char* gk, const char* gv,
                                                 char* dst, int t, int tid) {
    if (tid < 256) {
        const char* ksrc = gk + (size_t)t * KT * 32;   // contiguous 4 KB
        cpasync16(dst + KOFF + tid * 16, ksrc + tid * 16);
    }
    {
        int row = tid >> 4, c = tid & 15;
        cpasync16(dst + VOFF + row * 272 + c * 16,
                  gv + (size_t)row * (NP * 2) + t * 256 + c * 16);
    }
    CP_COMMIT();
}

// ============================================================================
// Kernel 2: HMMA flash attention; 512 thr, 16 warps = 4 qgroups x 4 ksplits
// ============================================================================
__global__ void __launch_bounds__(THREADS, 2) attn_kernel(
    const float* __restrict__ x, const float* __restrict__ Wo,
    const float* __restrict__ bo, const float* __restrict__ gamma,
    float* __restrict__ y)
{
    extern __shared__ char smc[];
    const int tid = threadIdx.x;
    const int w = tid >> 5, lane = tid & 31;
    const int wq = w & 3;            // query group (16 queries)
    const int wk = w >> 2;           // key quarter of each tile (32 keys)
    const int gr = lane >> 2, tg = lane & 3;
    const int b  = blockIdx.x / NQB;
    const int q0 = (blockIdx.x % NQB) * QB;

    float* sWo = (float*)(smc + WO_OFF);
    float* sbo = (float*)(smc + BO_OFF);
    float* sO  = (float*)(smc + SO_OFF);
    for (int i = tid; i < ICH * CCH; i += THREADS) sWo[i] = Wo[i];
    if (tid < CCH) sbo[tid] = bo[tid];

    // Q fragments for this warp's 16 queries (rows wq*16 + gr, +8)
    const u32* qp  = g_q2 + (size_t)(b * NP + q0 + wq * 16 + gr) * 16;
    const u32* qp8 = qp + 8 * 16;
    u32 qh[4], ql[4];
    qh[0] = qp[tg];     qh[1] = qp8[tg];     qh[2] = qp[tg + 4];  qh[3] = qp8[tg + 4];
    ql[0] = qp[8 + tg]; ql[1] = qp8[8 + tg]; ql[2] = qp[12 + tg]; ql[3] = qp8[12 + tg];

    const u32 one_b = (gr == 0) ? 0x3F803F80u : 0u;   // bf16 ones, col 0

    float oA[2][4] = {}, oC[2][4] = {};   // [cb][4]
    float oD[4] = {};                      // ones-column

    const char* gk = (const char*)(g_k2 + (size_t)b * NP * 8);
    const char* gv = (const char*)(g_vt + (size_t)b * 32 * NP);

    load_tile(gk, gv, smc + 0 * BUF_STRIDE, 0, tid);
    load_tile(gk, gv, smc + 1 * BUF_STRIDE, 1, tid);

    int bidx = 0;   // t % 3
    for (int t = 0; t < NT; t++) {
        if (t + 1 < NT) { asm volatile("cp.async.wait_group 1;" ::: "memory"); }
        else            { asm volatile("cp.async.wait_group 0;" ::: "memory"); }
        __syncthreads();
        if (t + 2 < NT) {
            int nb = bidx + 2; if (nb >= 3) nb -= 3;
            load_tile(gk, gv, smc + nb * BUF_STRIDE, t + 2, tid);
        }

        const char* kb = smc + bidx * BUF_STRIDE + KOFF;
        const char* vb = smc + bidx * BUF_STRIDE + VOFF;

        #pragma unroll
        for (int c2 = 0; c2 < 2; c2++) {
            const int ck = wk * 2 + c2;   // 16-key chunk (of 8 per tile)
            const char* ka = kb + (ck * 16 + gr) * 32 + tg * 8;
            uint2 kw0 = *(const uint2*)ka;
            uint2 kw1 = *(const uint2*)(ka + 8 * 32);
            uint2 vh[2], vl[2];
            #pragma unroll
            for (int cb = 0; cb < 2; cb++) {
                const char* va = vb + (cb * 8 + gr) * 272 + ck * 32 + tg * 8;
                vh[cb] = *(const uint2*)va;
                vl[cb] = *(const uint2*)(va + 16 * 272);
            }
            float sa0[4] = {0.f,0.f,0.f,0.f}, sb0[4] = {0.f,0.f,0.f,0.f};
            float sa1[4] = {0.f,0.f,0.f,0.f}, sb1[4] = {0.f,0.f,0.f,0.f};
            MMA_F16(sa0, qh, kw0.x, kw0.y);
            MMA_F16(sb0, ql, kw0.x, kw0.y);
            MMA_F16(sa1, qh, kw1.x, kw1.y);
            MMA_F16(sb1, ql, kw1.x, kw1.y);

            float p00 = ex2f(sa0[0] + sb0[0]), p01 = ex2f(sa0[1] + sb0[1]);
            float p02 = ex2f(sa0[2] + sb0[2]), p03 = ex2f(sa0[3] + sb0[3]);
            float p10 = ex2f(sa1[0] + sb1[0]), p11 = ex2f(sa1[1] + sb1[1]);
            float p12 = ex2f(sa1[2] + sb1[2]), p13 = ex2f(sa1[3] + sb1[3]);
            u32 pah[4];
            pah[0] = pack_bf16_rn(p00, p01); pah[1] = pack_bf16_rn(p02, p03);
            pah[2] = pack_bf16_rn(p10, p11); pah[3] = pack_bf16_rn(p12, p13);

            #pragma unroll
            for (int cb = 0; cb < 2; cb++) {
                MMA_BF16(oA[cb], pah, vh[cb].x, vh[cb].y);
                MMA_BF16(oC[cb], pah, vl[cb].x, vl[cb].y);
            }
            MMA_BF16(oD, pah, one_b, one_b);
        }
        if (++bidx == 3) bidx = 0;
    }

    float ro[2][4];
    #pragma unroll
    for (int cb = 0; cb < 2; cb++)
        #pragma unroll
        for (int i = 0; i < 4; i++)
            ro[cb][i] = oA[cb][i] + oC[cb][i];

    __syncthreads();   // tile buffers dead; alias partials
    float* part = (float*)smc;   // 3 slots x [64][18]
    const int qi0 = wq * 16 + gr, qi1 = qi0 + 8;
    if (wk > 0) {
        float* ps = part + (wk - 1) * 64 * 18;
        #pragma unroll
        for (int cb = 0; cb < 2; cb++) {
            int col = cb * 8 + tg * 2;
            ps[qi0 * 18 + col]     = ro[cb][0];
            ps[qi0 * 18 + col + 1] = ro[cb][1];
            ps[qi1 * 18 + col]     = ro[cb][2];
            ps[qi1 * 18 + col + 1] = ro[cb][3];
        }
        if (tg == 0) {
            ps[qi0 * 18 + 16] = oD[0];
            ps[qi1 * 18 + 16] = oD[2];
        }
    }
    __syncthreads();
    if (wk == 0) {
        float dnA = __shfl_sync(0xFFFFFFFFu, oD[0], lane & ~3);
        float dnB = __shfl_sync(0xFFFFFFFFu, oD[2], lane & ~3);
        #pragma unroll
        for (int k = 0; k < 3; k++) {
            dnA += part[k * 64 * 18 + qi0 * 18 + 16];
            dnB += part[k * 64 * 18 + qi1 * 18 + 16];
        }
        float id0 = 1.0f / dnA, id1 = 1.0f / dnB;
        #pragma unroll
        for (int cb = 0; cb < 2; cb++) {
            int col = cb * 8 + tg * 2;
            float a0 = ro[cb][0], a1 = ro[cb][1];
            float a2 = ro[cb][2], a3 = ro[cb][3];
            #pragma unroll
            for (int k = 0; k < 3; k++) {
                const float* ps = part + k * 64 * 18;
                a0 += ps[qi0 * 18 + col];     a1 += ps[qi0 * 18 + col + 1];
                a2 += ps[qi1 * 18 + col];     a3 += ps[qi1 * 18 + col + 1];
            }
            sO[qi0 * 17 + col]     = a0 * id0;
            sO[qi0 * 17 + col + 1] = a1 * id0;
            sO[qi1 * 17 + col]     = a2 * id1;
            sO[qi1 * 17 + col + 1] = a3 * id1;
        }
    }
    __syncthreads();

    // epilogue: y = gamma * (Wo @ O + bo) + x
    const float gam = gamma[0];
    for (int idx = tid; idx < CCH * QB; idx += THREADS) {
        int c = idx >> 6, q = idx & 63;
        const float* wr = sWo + c * ICH;
        const float* ov = sO + q * 17;
        float acc = 0.f;
        #pragma unroll
        for (int i = 0; i < ICH; i++) acc = fmaf(wr[i], ov[i], acc);
        size_t gi = ((size_t)(b * CCH + c)) * NP + (q0 + q);
        y[gi] = gam * (acc + sbo[c]) + x[gi];
    }
}

extern "C" void kernel_launch(void* const* d_in, const int* in_sizes, int n_in,
                              void* d_out, int out_size) {
    const float* x     = (const float*)d_in[0];
    const float* Wq    = (const float*)d_in[1];
    const float* bq    = (const float*)d_in[2];
    const float* Wk    = (const float*)d_in[3];
    const float* bk    = (const float*)d_in[4];
    const float* Wv    = (const float*)d_in[5];
    const float* bv    = (const float*)d_in[6];
    const float* Wo    = (const float*)d_in[7];
    const float* bo    = (const float*)d_in[8];
    const float* gamma = (const float*)d_in[9];
    float* y = (float*)d_out;

    cudaFuncSetAttribute(attn_kernel, cudaFuncAttributeMaxDynamicSharedMemorySize, SMEM_BYTES);

    qkv_kernel<<<(BATCH * NP) / 256, 256>>>(x, Wq, bq, Wk, bk, Wv, bv);
    attn_kernel<<<BATCH * NQB, THREADS, SMEM_BYTES>>>(x, Wo, bo, gamma, y);
}

// round 16
// speedup vs baseline: 1.1191x; 1.0841x over previous
#include <cuda_runtime.h>
#include <cuda_fp16.h>
#include <cstdint>

#define BATCH 2
#define CCH 128
#define ICH 16
#define NP 9216
#define QB 64                // queries per CTA
#define KT 128               // keys per tile
#define NT (NP / KT)         // 72
#define NQB (NP / QB)        // 144
#define LOG2E 1.4426950408889634f
#define THREADS 512

// smem: 3 buffers of (K: 4KB) + (V: 8KB), fused-fragment layout
#define BUF_STRIDE 12288
#define KOFF 0
#define VOFF 4096
#define WO_OFF 36864
#define BO_OFF 45056
#define SO_OFF 45568
#define SMEM_BYTES 49920
// cross-warp partials alias buffer region after mainloop: 3 slots x [64][18]

typedef unsigned int u32;

// K global: per batch, per 128-key tile (4KB): [ck][jr][tg][16B = key jr | key jr+8]
__device__ __align__(16) u32 g_k2[BATCH * NP * 8];
// V global: per batch, per tile (8KB): [ck][p 0..16][tg][16B = ch p | ch p+8], p>=8 -> Vl
__device__ __align__(16) unsigned short g_vt[BATCH * 32 * NP];
__device__ __align__(16) u32 g_q2[BATCH * NP * 16];   // per query: 8 fp16-hi pair words, 8 lo

static __device__ __forceinline__ float ex2f(float x) {
    float r; asm("ex2.approx.f32 %0, %1;" : "=f"(r) : "f"(x)); return r;
}
static __device__ __forceinline__ u32 pack_bf16_rn(float p0, float p1) {
    u32 d; asm("cvt.rn.satfinite.bf16x2.f32 %0, %1, %2;" : "=r"(d) : "f"(p1), "f"(p0)); return d;
}
static __device__ __forceinline__ float lo_of(float a) {
    return a - __uint_as_float(__float_as_uint(a) & 0xFFFF0000u);
}
static __device__ __forceinline__ u32 pack_f16(__half a, __half b) {
    return (u32)__half_as_ushort(a) | ((u32)__half_as_ushort(b) << 16);
}
static __device__ __forceinline__ void cpasync16(void* s, const void* g) {
    u32 a = (u32)__cvta_generic_to_shared(s);
    asm volatile("cp.async.cg.shared.global [%0], [%1], 16;" :: "r"(a), "l"(g));
}
#define CP_COMMIT() asm volatile("cp.async.commit_group;" ::: "memory")

#define MMA_F16(d, a, b0, b1) \
    asm volatile("mma.sync.aligned.m16n8k16.row.col.f32.f16.f16.f32 " \
        "{%0,%1,%2,%3},{%4,%5,%6,%7},{%8,%9},{%0,%1,%2,%3};" \
        : "+f"((d)[0]), "+f"((d)[1]), "+f"((d)[2]), "+f"((d)[3]) \
        : "r"((a)[0]), "r"((a)[1]), "r"((a)[2]), "r"((a)[3]), "r"(b0), "r"(b1))

#define MMA_BF16(d, a, b0, b1) \
    asm volatile("mma.sync.aligned.m16n8k16.row.col.f32.bf16.bf16.f32 " \
        "{%0,%1,%2,%3},{%4,%5,%6,%7},{%8,%9},{%0,%1,%2,%3};" \
        : "+f"((d)[0]), "+f"((d)[1]), "+f"((d)[2]), "+f"((d)[3]) \
        : "r"((a)[0]), "r"((a)[1]), "r"((a)[2]), "r"((a)[3]), "r"(b0), "r"(b1))

// ============================================================================
// Kernel 1: qkv projections -> fp16 hi/lo Q ; fp16 K ; bf16 hi/lo V
// K/V written in the fused-fragment tile layout (see attn kernel).
// ============================================================================
__global__ void __launch_bounds__(256) qkv_kernel(
    const float* __restrict__ x,
    const float* __restrict__ Wq, const float* __restrict__ bq,
    const float* __restrict__ Wk, const float* __restrict__ bk,
    const float* __restrict__ Wv, const float* __restrict__ bv)
{
    __shared__ float sWq[ICH * CCH], sWk[ICH * CCH], sWv[ICH * CCH];
    __shared__ float sb[3 * ICH];
    for (int i = threadIdx.x; i < ICH * CCH; i += 256) {
        sWq[i] = Wq[i]; sWk[i] = Wk[i]; sWv[i] = Wv[i];
    }
    if (threadIdx.x < ICH)            sb[threadIdx.x] = bq[threadIdx.x];
    else if (threadIdx.x < 2 * ICH)   sb[threadIdx.x] = bk[threadIdx.x - ICH];
    else if (threadIdx.x < 3 * ICH)   sb[threadIdx.x] = bv[threadIdx.x - 2 * ICH];
    __syncthreads();

    int gid = blockIdx.x * 256 + threadIdx.x;
    int b = gid / NP, n = gid % NP;
    const float* xb = x + (size_t)b * CCH * NP + n;

    float aq[ICH], ak[ICH], av[ICH];
    #pragma unroll
    for (int i = 0; i < ICH; i++) { aq[i] = 0.f; ak[i] = 0.f; av[i] = 0.f; }

    for (int c = 0; c < CCH; c += 4) {
        float x0 = xb[(size_t)(c + 0) * NP];
        float x1 = xb[(size_t)(c + 1) * NP];
        float x2 = xb[(size_t)(c + 2) * NP];
        float x3 = xb[(size_t)(c + 3) * NP];
        #pragma unroll
        for (int i = 0; i < ICH; i++) {
            float4 wq = *(const float4*)&sWq[i * CCH + c];
            aq[i] = fmaf(wq.x, x0, fmaf(wq.y, x1, fmaf(wq.z, x2, fmaf(wq.w, x3, aq[i]))));
            float4 wk = *(const float4*)&sWk[i * CCH + c];
            ak[i] = fmaf(wk.x, x0, fmaf(wk.y, x1, fmaf(wk.z, x2, fmaf(wk.w, x3, ak[i]))));
            float4 wv = *(const float4*)&sWv[i * CCH + c];
            av[i] = fmaf(wv.x, x0, fmaf(wv.y, x1, fmaf(wv.z, x2, fmaf(wv.w, x3, av[i]))));
        }
    }

    float qf[ICH], kf[ICH];
    #pragma unroll
    for (int i = 0; i < ICH; i++) {
        qf[i] = (aq[i] + sb[i]) * LOG2E;
        kf[i] = ak[i] + sb[ICH + i];
    }
    u32 qhi[8], qlo[8], khi[8];
    #pragma unroll
    for (int j = 0; j < 8; j++) {
        __half qh0 = __float2half_rn(qf[2 * j]),     qh1 = __float2half_rn(qf[2 * j + 1]);
        float  qlo0 = qf[2 * j] - __half2float(qh0), qlo1 = qf[2 * j + 1] - __half2float(qh1);
        qhi[j] = pack_f16(qh0, qh1);
        qlo[j] = pack_f16(__float2half_rn(qlo0), __float2half_rn(qlo1));
        khi[j] = pack_f16(__float2half_rn(kf[2 * j]), __float2half_rn(kf[2 * j + 1]));
    }
    u32* qo = g_q2 + (size_t)gid * 16;
    #pragma unroll
    for (int j = 0; j < 8; j++) { qo[j] = qhi[j]; qo[8 + j] = qlo[j]; }

    const int tile = n >> 7, nl = n & 127;
    const int ck = nl >> 4, j16 = nl & 15;
    // K fused-fragment write: [ck][jr][tg][16B = key jr | key jr+8]
    {
        int jr = j16 & 7, h = j16 >> 3;
        u32* kb = g_k2 + (size_t)b * NP * 8 + tile * 1024 + ck * 128 + jr * 16 + h * 2;
        #pragma unroll
        for (int tg = 0; tg < 4; tg++) {
            kb[tg * 4 + 0] = khi[tg];
            kb[tg * 4 + 1] = khi[tg + 4];
        }
    }
    // V fused-fragment write (with intra-16 key permutation for B-fragment order)
    {
        int p_ = j16 >> 1, e = j16 & 1;
        int pp = (p_ < 4) ? (2 * p_) : (2 * (p_ - 4) + 1);
        int s = pp * 2 + e;
        int vtg = s >> 2, pos = s & 3;
        unsigned short* vb = g_vt + (size_t)b * 32 * NP + tile * 4096 + ck * 512 + vtg * 8 + pos;
        #pragma unroll
        for (int i = 0; i < ICH; i++) {
            float vv = av[i] + sb[2 * ICH + i];
            int p = i & 7, h = i >> 3;
            vb[p * 32 + h * 4]       = (unsigned short)(__float_as_uint(vv) >> 16);
            vb[(8 + p) * 32 + h * 4] = (unsigned short)(__float_as_uint(lo_of(vv)) >> 16);
        }
    }
}

// ---------------- tile loader (512 threads; contiguous copies) ----------------
static __device__ __forceinline__ void load_tile(const char* gk, const char* gv,
                                                 char* dst, int t, int tid) {
    if (tid < 256)
        cpasync16(dst + KOFF + tid * 16, gk + (size_t)t * 4096 + tid * 16);
    cpasync16(dst + VOFF + tid * 16, gv + (size_t)t * 8192 + tid * 16);
    CP_COMMIT();
}

// ============================================================================
// Kernel 2: HMMA flash attention; 512 thr, LDS.128 fused fragments
// ============================================================================
__global__ void __launch_bounds__(THREADS, 2) attn_kernel(
    const float* __restrict__ x, const float* __restrict__ Wo,
    const float* __restrict__ bo, const float* __restrict__ gamma,
    float* __restrict__ y)
{
    extern __shared__ char smc[];
    const int tid = threadIdx.x;
    const int w = tid >> 5, lane = tid & 31;
    const int wq = w & 3;            // query group (16 queries)
    const int wk = w >> 2;           // key quarter of each tile (32 keys)
    const int gr = lane >> 2, tg = lane & 3;
    const int b  = blockIdx.x / NQB;
    const int q0 = (blockIdx.x % NQB) * QB;

    float* sWo = (float*)(smc + WO_OFF);
    float* sbo = (float*)(smc + BO_OFF);
    float* sO  = (float*)(smc + SO_OFF);
    for (int i = tid; i < ICH * CCH; i += THREADS) sWo[i] = Wo[i];
    if (tid < CCH) sbo[tid] = bo[tid];

    // Q fragments for this warp's 16 queries (rows wq*16 + gr, +8)
    const u32* qp  = g_q2 + (size_t)(b * NP + q0 + wq * 16 + gr) * 16;
    const u32* qp8 = qp + 8 * 16;
    u32 qh[4], ql[4];
    qh[0] = qp[tg];     qh[1] = qp8[tg];     qh[2] = qp[tg + 4];  qh[3] = qp8[tg + 4];
    ql[0] = qp[8 + tg]; ql[1] = qp8[8 + tg]; ql[2] = qp[12 + tg]; ql[3] = qp8[12 + tg];

    const u32 one_b = (gr == 0) ? 0x3F803F80u : 0u;   // bf16 ones, col 0

    float oA[2][4] = {}, oC[2][4] = {};   // [cb][4]
    float oD[4] = {};                      // ones-column (denominator)

    const char* gk = (const char*)g_k2 + (size_t)b * NP * 32;
    const char* gv = (const char*)g_vt + (size_t)b * NP * 64;

    // per-warp static smem sub-offsets
    const u32 kw_off = KOFF + (wk * 2) * 512 + gr * 64 + tg * 16;
    const u32 vw_off = VOFF + (wk * 2) * 1024 + gr * 64 + tg * 16;

    load_tile(gk, gv, smc + 0 * BUF_STRIDE, 0, tid);
    load_tile(gk, gv, smc + 1 * BUF_STRIDE, 1, tid);

    int bidx = 0;   // t % 3
    for (int t = 0; t < NT; t++) {
        if (t + 1 < NT) { asm volatile("cp.async.wait_group 1;" ::: "memory"); }
        else            { asm volatile("cp.async.wait_group 0;" ::: "memory"); }
        __syncthreads();
        if (t + 2 < NT) {
            int nb = bidx + 2; if (nb >= 3) nb -= 3;
            load_tile(gk, gv, smc + nb * BUF_STRIDE, t + 2, tid);
        }

        const char* kb = smc + bidx * BUF_STRIDE + kw_off;
        const char* vb = smc + bidx * BUF_STRIDE + vw_off;

        #pragma unroll
        for (int c2 = 0; c2 < 2; c2++) {
            uint4 kw = *(const uint4*)(kb + c2 * 512);          // key gr | key gr+8
            uint4 vh = *(const uint4*)(vb + c2 * 1024);         // ch gr | ch gr+8 (Vh)
            uint4 vl = *(const uint4*)(vb + c2 * 1024 + 512);   // (Vl)

            float sa0[4] = {0.f,0.f,0.f,0.f};
            float sa1[4] = {0.f,0.f,0.f,0.f};
            MMA_F16(sa0, qh, kw.x, kw.y);
            MMA_F16(sa0, ql, kw.x, kw.y);
            MMA_F16(sa1, qh, kw.z, kw.w);
            MMA_F16(sa1, ql, kw.z, kw.w);

            float p00 = ex2f(sa0[0]), p01 = ex2f(sa0[1]);
            float p02 = ex2f(sa0[2]), p03 = ex2f(sa0[3]);
            float p10 = ex2f(sa1[0]), p11 = ex2f(sa1[1]);
            float p12 = ex2f(sa1[2]), p13 = ex2f(sa1[3]);
            u32 pah[4];
            pah[0] = pack_bf16_rn(p00, p01); pah[1] = pack_bf16_rn(p02, p03);
            pah[2] = pack_bf16_rn(p10, p11); pah[3] = pack_bf16_rn(p12, p13);

            MMA_BF16(oA[0], pah, vh.x, vh.y);
            MMA_BF16(oA[1], pah, vh.z, vh.w);
            MMA_BF16(oC[0], pah, vl.x, vl.y);
            MMA_BF16(oC[1], pah, vl.z, vl.w);
            MMA_BF16(oD, pah, one_b, one_b);
        }
        if (++bidx == 3) bidx = 0;
    }

    float ro[2][4];
    #pragma unroll
    for (int cb = 0; cb < 2; cb++)
        #pragma unroll
        for (int i = 0; i < 4; i++)
            ro[cb][i] = oA[cb][i] + oC[cb][i];

    __syncthreads();   // tile buffers dead; alias partials
    float* part = (float*)smc;   // 3 slots x [64][18]
    const int qi0 = wq * 16 + gr, qi1 = qi0 + 8;
    if (wk > 0) {
        float* ps = part + (wk - 1) * 64 * 18;
        #pragma unroll
        for (int cb = 0; cb < 2; cb++) {
            int col = cb * 8 + tg * 2;
            ps[qi0 * 18 + col]     = ro[cb][0];
            ps[qi0 * 18 + col + 1] = ro[cb][1];
            ps[qi1 * 18 + col]     = ro[cb][2];
            ps[qi1 * 18 + col + 1] = ro[cb][3];
        }
        if (tg == 0) {
            ps[qi0 * 18 + 16] = oD[0];
            ps[qi1 * 18 + 16] = oD[2];
        }
    }
    __syncthreads();
    if (wk == 0) {
        float dnA = __shfl_sync(0xFFFFFFFFu, oD[0], lane & ~3);
        float dnB = __shfl_sync(0xFFFFFFFFu, oD[2], lane & ~3);
        #pragma unroll
        for (int k = 0; k < 3; k++) {
            dnA += part[k * 64 * 18 + qi0 * 18 + 16];
            dnB += part[k * 64 * 18 + qi1 * 18 + 16];
        }
        float id0 = 1.0f / dnA, id1 = 1.0f / dnB;
        #pragma unroll
        for (int cb = 0; cb < 2; cb++) {
            int col = cb * 8 + tg * 2;
            float a0 = ro[cb][0], a1 = ro[cb][1];
            float a2 = ro[cb][2], a3 = ro[cb][3];
            #pragma unroll
            for (int k = 0; k < 3; k++) {
                const float* ps = part + k * 64 * 18;
                a0 += ps[qi0 * 18 + col];     a1 += ps[qi0 * 18 + col + 1];
                a2 += ps[qi1 * 18 + col];     a3 += ps[qi1 * 18 + col + 1];
            }
            sO[qi0 * 17 + col]     = a0 * id0;
            sO[qi0 * 17 + col + 1] = a1 * id0;
            sO[qi1 * 17 + col]     = a2 * id1;
            sO[qi1 * 17 + col + 1] = a3 * id1;
        }
    }
    __syncthreads();

    // epilogue: y = gamma * (Wo @ O + bo) + x
    const float gam = gamma[0];
    for (int idx = tid; idx < CCH * QB; idx += THREADS) {
        int c = idx >> 6, q = idx & 63;
        const float* wr = sWo + c * ICH;
        const float* ov = sO + q * 17;
        float acc = 0.f;
        #pragma unroll
        for (int i = 0; i < ICH; i++) acc = fmaf(wr[i], ov[i], acc);
        size_t gi = ((size_t)(b * CCH + c)) * NP + (q0 + q);
        y[gi] = gam * (acc + sbo[c]) + x[gi];
    }
}

extern "C" void kernel_launch(void* const* d_in, const int* in_sizes, int n_in,
                              void* d_out, int out_size) {
    const float* x     = (const float*)d_in[0];
    const float* Wq    = (const float*)d_in[1];
    const float* bq    = (const float*)d_in[2];
    const float* Wk    = (const float*)d_in[3];
    const float* bk    = (const float*)d_in[4];
    const float* Wv    = (const float*)d_in[5];
    const float* bv    = (const float*)d_in[6];
    const float* Wo    = (const float*)d_in[7];
    const float* bo    = (const float*)d_in[8];
    const float* gamma = (const float*)d_in[9];
    float* y = (float*)d_out;

    cudaFuncSetAttribute(attn_kernel, cudaFuncAttributeMaxDynamicSharedMemorySize, SMEM_BYTES);

    qkv_kernel<<<(BATCH * NP) / 256, 256>>>(x, Wq, bq, Wk, bk, Wv, bv);
    attn_kernel<<<BATCH * NQB, THREADS, SMEM_BYTES>>>(x, Wo, bo, gamma, y);
}

// round 17
// speedup vs baseline: 1.2218x; 1.0918x over previous
#include <cuda_runtime.h>
#include <cuda_fp16.h>
#include <cstdint>

#define BATCH 2
#define CCH 128
#define ICH 16
#define NP 9216
#define QB 64                // queries per CTA
#define KT 256               // keys per tile
#define NT (NP / KT)         // 36
#define NQB (NP / QB)        // 144
#define LOG2E 1.4426950408889634f
#define THREADS 512

// smem: 3 buffers of (K: 8KB) + (V: 16KB), fused-fragment layout
#define BUF_STRIDE 24576
#define KOFF 0
#define VOFF 8192
#define WO_OFF 73728
#define BO_OFF 81920
#define SO_OFF 82432
#define SMEM_BYTES 86784
// cross-warp partials alias buffer region after mainloop: 3 slots x [64][18]

typedef unsigned int u32;

// K global: per batch, per 128-key block (4KB): [ck][jr][tg][16B = key jr | key jr+8]
__device__ __align__(16) u32 g_k2[BATCH * NP * 8];
// V global: per batch, per 128-key block (8KB): [ck][p 0..16][tg][16B = ch p | ch p+8], p>=8 -> Vl
__device__ __align__(16) unsigned short g_vt[BATCH * 32 * NP];
__device__ __align__(16) u32 g_q2[BATCH * NP * 16];   // per query: 8 fp16-hi pair words, 8 lo

static __device__ __forceinline__ float ex2f(float x) {
    float r; asm("ex2.approx.f32 %0, %1;" : "=f"(r) : "f"(x)); return r;
}
static __device__ __forceinline__ u32 pack_bf16_rn(float p0, float p1) {
    u32 d; asm("cvt.rn.satfinite.bf16x2.f32 %0, %1, %2;" : "=r"(d) : "f"(p1), "f"(p0)); return d;
}
static __device__ __forceinline__ float lo_of(float a) {
    return a - __uint_as_float(__float_as_uint(a) & 0xFFFF0000u);
}
static __device__ __forceinline__ u32 pack_f16(__half a, __half b) {
    return (u32)__half_as_ushort(a) | ((u32)__half_as_ushort(b) << 16);
}
static __device__ __forceinline__ void cpasync16(void* s, const void* g) {
    u32 a = (u32)__cvta_generic_to_shared(s);
    asm volatile("cp.async.cg.shared.global [%0], [%1], 16;" :: "r"(a), "l"(g));
}
#define CP_COMMIT() asm volatile("cp.async.commit_group;" ::: "memory")

#define MMA_F16(d, a, b0, b1) \
    asm volatile("mma.sync.aligned.m16n8k16.row.col.f32.f16.f16.f32 " \
        "{%0,%1,%2,%3},{%4,%5,%6,%7},{%8,%9},{%0,%1,%2,%3};" \
        : "+f"((d)[0]), "+f"((d)[1]), "+f"((d)[2]), "+f"((d)[3]) \
        : "r"((a)[0]), "r"((a)[1]), "r"((a)[2]), "r"((a)[3]), "r"(b0), "r"(b1))

#define MMA_BF16(d, a, b0, b1) \
    asm volatile("mma.sync.aligned.m16n8k16.row.col.f32.bf16.bf16.f32 " \
        "{%0,%1,%2,%3},{%4,%5,%6,%7},{%8,%9},{%0,%1,%2,%3};" \
        : "+f"((d)[0]), "+f"((d)[1]), "+f"((d)[2]), "+f"((d)[3]) \
        : "r"((a)[0]), "r"((a)[1]), "r"((a)[2]), "r"((a)[3]), "r"(b0), "r"(b1))

// ============================================================================
// Kernel 1: qkv projections, 2 threads per voxel (64 channels each) + shfl
// combine. grid=144 -> all SMs active, FFMA per warp halved vs 1-thread/voxel.
// ============================================================================
__global__ void __launch_bounds__(256) qkv_kernel(
    const float* __restrict__ x,
    const float* __restrict__ Wq, const float* __restrict__ bq,
    const float* __restrict__ Wk, const float* __restrict__ bk,
    const float* __restrict__ Wv, const float* __restrict__ bv)
{
    __shared__ float sWq[ICH * CCH], sWk[ICH * CCH], sWv[ICH * CCH];
    __shared__ float sb[3 * ICH];
    for (int i = threadIdx.x; i < ICH * CCH; i += 256) {
        sWq[i] = Wq[i]; sWk[i] = Wk[i]; sWv[i] = Wv[i];
    }
    if (threadIdx.x < ICH)            sb[threadIdx.x] = bq[threadIdx.x];
    else if (threadIdx.x < 2 * ICH)   sb[threadIdx.x] = bk[threadIdx.x - ICH];
    else if (threadIdx.x < 3 * ICH)   sb[threadIdx.x] = bv[threadIdx.x - 2 * ICH];
    __syncthreads();

    const int tid = threadIdx.x;
    const int h = tid & 1;                              // channel half
    const int gvox = blockIdx.x * 128 + (tid >> 1);     // voxel id
    const int b = gvox / NP, n = gvox % NP;
    const float* xb = x + (size_t)b * CCH * NP + n;
    const int c0 = h * 64;

    float aq[ICH], ak[ICH], av[ICH];
    #pragma unroll
    for (int i = 0; i < ICH; i++) { aq[i] = 0.f; ak[i] = 0.f; av[i] = 0.f; }

    for (int c = c0; c < c0 + 64; c += 4) {
        float x0 = xb[(size_t)(c + 0) * NP];
        float x1 = xb[(size_t)(c + 1) * NP];
        float x2 = xb[(size_t)(c + 2) * NP];
        float x3 = xb[(size_t)(c + 3) * NP];
        #pragma unroll
        for (int i = 0; i < ICH; i++) {
            float4 wq = *(const float4*)&sWq[i * CCH + c];
            aq[i] = fmaf(wq.x, x0, fmaf(wq.y, x1, fmaf(wq.z, x2, fmaf(wq.w, x3, aq[i]))));
            float4 wk = *(const float4*)&sWk[i * CCH + c];
            ak[i] = fmaf(wk.x, x0, fmaf(wk.y, x1, fmaf(wk.z, x2, fmaf(wk.w, x3, ak[i]))));
            float4 wv = *(const float4*)&sWv[i * CCH + c];
            av[i] = fmaf(wv.x, x0, fmaf(wv.y, x1, fmaf(wv.z, x2, fmaf(wv.w, x3, av[i]))));
        }
    }
    // combine the two channel halves (lane pairs)
    #pragma unroll
    for (int i = 0; i < ICH; i++) {
        aq[i] += __shfl_xor_sync(0xFFFFFFFFu, aq[i], 1);
        ak[i] += __shfl_xor_sync(0xFFFFFFFFu, ak[i], 1);
        av[i] += __shfl_xor_sync(0xFFFFFFFFu, av[i], 1);
    }

    const int tile = n >> 7, nl = n & 127;
    const int ck = nl >> 4, j16 = nl & 15;

    if (h == 0) {
        // Q: fp16 hi/lo
        u32* qo = g_q2 + (size_t)gvox * 16;
        #pragma unroll
        for (int j = 0; j < 8; j++) {
            float q0 = (aq[2 * j] + sb[2 * j]) * LOG2E;
            float q1 = (aq[2 * j + 1] + sb[2 * j + 1]) * LOG2E;
            __half qh0 = __float2half_rn(q0), qh1 = __float2half_rn(q1);
            qo[j]     = pack_f16(qh0, qh1);
            qo[8 + j] = pack_f16(__float2half_rn(q0 - __half2float(qh0)),
                                 __float2half_rn(q1 - __half2float(qh1)));
        }
    } else {
        // K: fp16 single, fused-fragment layout
        u32 khi[8];
        #pragma unroll
        for (int j = 0; j < 8; j++)
            khi[j] = pack_f16(__float2half_rn(ak[2 * j] + sb[ICH + 2 * j]),
                              __float2half_rn(ak[2 * j + 1] + sb[ICH + 2 * j + 1]));
        int jr = j16 & 7, hh = j16 >> 3;
        u32* kb = g_k2 + (size_t)b * NP * 8 + tile * 1024 + ck * 128 + jr * 16 + hh * 2;
        #pragma unroll
        for (int tg = 0; tg < 4; tg++) {
            kb[tg * 4 + 0] = khi[tg];
            kb[tg * 4 + 1] = khi[tg + 4];
        }
        // V: bf16 hi/lo, fused-fragment layout with intra-16 key permutation
        int p_ = j16 >> 1, e = j16 & 1;
        int pp = (p_ < 4) ? (2 * p_) : (2 * (p_ - 4) + 1);
        int s = pp * 2 + e;
        int vtg = s >> 2, pos = s & 3;
        unsigned short* vb = g_vt + (size_t)b * 32 * NP + tile * 4096 + ck * 512 + vtg * 8 + pos;
        #pragma unroll
        for (int i = 0; i < ICH; i++) {
            float vv = av[i] + sb[2 * ICH + i];
            int p = i & 7, hb = i >> 3;
            vb[p * 32 + hb * 4]       = (unsigned short)(__float_as_uint(vv) >> 16);
            vb[(8 + p) * 32 + hb * 4] = (unsigned short)(__float_as_uint(lo_of(vv)) >> 16);
        }
    }
}

// ---------------- tile loader (512 threads; contiguous copies, KT=256) ------
static __device__ __forceinline__ void load_tile(const char* gk, const char* gv,
                                                 char* dst, int t, int tid) {
    cpasync16(dst + KOFF + tid * 16, gk + (size_t)t * 8192 + tid * 16);
    #pragma unroll
    for (int r = 0; r < 2; r++) {
        int idx = r * 512 + tid;
        cpasync16(dst + VOFF + idx * 16, gv + (size_t)t * 16384 + idx * 16);
    }
    CP_COMMIT();
}

// ============================================================================
// Kernel 2: HMMA flash attention; 512 thr, KT=256, LDS.128 fused fragments
// ============================================================================
__global__ void __launch_bounds__(THREADS, 2) attn_kernel(
    const float* __restrict__ x, const float* __restrict__ Wo,
    const float* __restrict__ bo, const float* __restrict__ gamma,
    float* __restrict__ y)
{
    extern __shared__ char smc[];
    const int tid = threadIdx.x;
    const int w = tid >> 5, lane = tid & 31;
    const int wq = w & 3;            // query group (16 queries)
    const int wk = w >> 2;           // key quarter of each tile (64 keys)
    const int gr = lane >> 2, tg = lane & 3;
    const int b  = blockIdx.x / NQB;
    const int q0 = (blockIdx.x % NQB) * QB;

    float* sWo = (float*)(smc + WO_OFF);
    float* sbo = (float*)(smc + BO_OFF);
    float* sO  = (float*)(smc + SO_OFF);
    for (int i = tid; i < ICH * CCH; i += THREADS) sWo[i] = Wo[i];
    if (tid < CCH) sbo[tid] = bo[tid];

    // Q fragments for this warp's 16 queries (rows wq*16 + gr, +8)
    const u32* qp  = g_q2 + (size_t)(b * NP + q0 + wq * 16 + gr) * 16;
    const u32* qp8 = qp + 8 * 16;
    u32 qh[4], ql[4];
    qh[0] = qp[tg];     qh[1] = qp8[tg];     qh[2] = qp[tg + 4];  qh[3] = qp8[tg + 4];
    ql[0] = qp[8 + tg]; ql[1] = qp8[8 + tg]; ql[2] = qp[12 + tg]; ql[3] = qp8[12 + tg];

    const u32 one_b = (gr == 0) ? 0x3F803F80u : 0u;   // bf16 ones, col 0

    float oA[2][4] = {}, oC[2][4] = {};   // [cb][4]
    float oD[4] = {};                      // ones-column (denominator)

    const char* gk = (const char*)g_k2 + (size_t)b * NP * 32;
    const char* gv = (const char*)g_vt + (size_t)b * NP * 64;

    // per-warp static smem sub-offsets (chunk = wk*4 + c2, 16 chunks/tile)
    const u32 kw_off = KOFF + (wk >> 1) * 4096 + (wk & 1) * 2048 + gr * 64 + tg * 16;
    const u32 vw_off = VOFF + (wk >> 1) * 8192 + (wk & 1) * 4096 + gr * 64 + tg * 16;

    load_tile(gk, gv, smc + 0 * BUF_STRIDE, 0, tid);
    load_tile(gk, gv, smc + 1 * BUF_STRIDE, 1, tid);

    int bidx = 0;   // t % 3
    for (int t = 0; t < NT; t++) {
        if (t + 1 < NT) { asm volatile("cp.async.wait_group 1;" ::: "memory"); }
        else            { asm volatile("cp.async.wait_group 0;" ::: "memory"); }
        __syncthreads();
        if (t + 2 < NT) {
            int nb = bidx + 2; if (nb >= 3) nb -= 3;
            load_tile(gk, gv, smc + nb * BUF_STRIDE, t + 2, tid);
        }

        const char* kb = smc + bidx * BUF_STRIDE + kw_off;
        const char* vb = smc + bidx * BUF_STRIDE + vw_off;

        #pragma unroll
        for (int c2 = 0; c2 < 4; c2++) {
            uint4 kw = *(const uint4*)(kb + c2 * 512);          // key gr | key gr+8
            uint4 vh = *(const uint4*)(vb + c2 * 1024);         // ch gr | ch gr+8 (Vh)
            uint4 vl = *(const uint4*)(vb + c2 * 1024 + 512);   // (Vl)

            float sa0[4] = {0.f,0.f,0.f,0.f};
            float sa1[4] = {0.f,0.f,0.f,0.f};
            MMA_F16(sa0, qh, kw.x, kw.y);
            MMA_F16(sa0, ql, kw.x, kw.y);
            MMA_F16(sa1, qh, kw.z, kw.w);
            MMA_F16(sa1, ql, kw.z, kw.w);

            float p00 = ex2f(sa0[0]), p01 = ex2f(sa0[1]);
            float p02 = ex2f(sa0[2]), p03 = ex2f(sa0[3]);
            float p10 = ex2f(sa1[0]), p11 = ex2f(sa1[1]);
            float p12 = ex2f(sa1[2]), p13 = ex2f(sa1[3]);
            u32 pah[4];
            pah[0] = pack_bf16_rn(p00, p01); pah[1] = pack_bf16_rn(p02, p03);
            pah[2] = pack_bf16_rn(p10, p11); pah[3] = pack_bf16_rn(p12, p13);

            MMA_BF16(oA[0], pah, vh.x, vh.y);
            MMA_BF16(oA[1], pah, vh.z, vh.w);
            MMA_BF16(oC[0], pah, vl.x, vl.y);
            MMA_BF16(oC[1], pah, vl.z, vl.w);
            MMA_BF16(oD, pah, one_b, one_b);
        }
        if (++bidx == 3) bidx = 0;
    }

    float ro[2][4];
    #pragma unroll
    for (int cb = 0; cb < 2; cb++)
        #pragma unroll
        for (int i = 0; i < 4; i++)
            ro[cb][i] = oA[cb][i] + oC[cb][i];

    __syncthreads();   // tile buffers dead; alias partials
    float* part = (float*)smc;   // 3 slots x [64][18]
    const int qi0 = wq * 16 + gr, qi1 = qi0 + 8;
    if (wk > 0) {
        float* ps = part + (wk - 1) * 64 * 18;
        #pragma unroll
        for (int cb = 0; cb < 2; cb++) {
            int col = cb * 8 + tg * 2;
            ps[qi0 * 18 + col]     = ro[cb][0];
            ps[qi0 * 18 + col + 1] = ro[cb][1];
            ps[qi1 * 18 + col]     = ro[cb][2];
            ps[qi1 * 18 + col + 1] = ro[cb][3];
        }
        if (tg == 0) {
            ps[qi0 * 18 + 16] = oD[0];
            ps[qi1 * 18 + 16] = oD[2];
        }
    }
    __syncthreads();
    if (wk == 0) {
        float dnA = __shfl_sync(0xFFFFFFFFu, oD[0], lane & ~3);
        float dnB = __shfl_sync(0xFFFFFFFFu, oD[2], lane & ~3);
        #pragma unroll
        for (int k = 0; k < 3; k++) {
            dnA += part[k * 64 * 18 + qi0 * 18 + 16];
            dnB += part[k * 64 * 18 + qi1 * 18 + 16];
        }
        float id0 = 1.0f / dnA, id1 = 1.0f / dnB;
        #pragma unroll
        for (int cb = 0; cb < 2; cb++) {
            int col = cb * 8 + tg * 2;
            float a0 = ro[cb][0], a1 = ro[cb][1];
            float a2 = ro[cb][2], a3 = ro[cb][3];
            #pragma unroll
            for (int k = 0; k < 3; k++) {
                const float* ps = part + k * 64 * 18;
                a0 += ps[qi0 * 18 + col];     a1 += ps[qi0 * 18 + col + 1];
                a2 += ps[qi1 * 18 + col];     a3 += ps[qi1 * 18 + col + 1];
            }
            sO[qi0 * 17 + col]     = a0 * id0;
            sO[qi0 * 17 + col + 1] = a1 * id0;
            sO[qi1 * 17 + col]     = a2 * id1;
            sO[qi1 * 17 + col + 1] = a3 * id1;
        }
    }
    __syncthreads();

    // epilogue: y = gamma * (Wo @ O + bo) + x
    const float gam = gamma[0];
    for (int idx = tid; idx < CCH * QB; idx += THREADS) {
        int c = idx >> 6, q = idx & 63;
        const float* wr = sWo + c * ICH;
        const float* ov = sO + q * 17;
        float acc = 0.f;
        #pragma unroll
        for (int i = 0; i < ICH; i++) acc = fmaf(wr[i], ov[i], acc);
        size_t gi = ((size_t)(b * CCH + c)) * NP + (q0 + q);
        y[gi] = gam * (acc + sbo[c]) + x[gi];
    }
}

extern "C" void kernel_launch(void* const* d_in, const int* in_sizes, int n_in,
                              void* d_out, int out_size) {
    const float* x     = (const float*)d_in[0];
    const float* Wq    = (const float*)d_in[1];
    const float* bq    = (const float*)d_in[2];
    const float* Wk    = (const float*)d_in[3];
    const float* bk    = (const float*)d_in[4];
    const float* Wv    = (const float*)d_in[5];
    const float* bv    = (const float*)d_in[6];
    const float* Wo    = (const float*)d_in[7];
    const float* bo    = (const float*)d_in[8];
    const float* gamma = (const float*)d_in[9];
    float* y = (float*)d_out;

    cudaFuncSetAttribute(attn_kernel, cudaFuncAttributeMaxDynamicSharedMemorySize, SMEM_BYTES);

    qkv_kernel<<<(BATCH * NP) / 128, 256>>>(x, Wq, bq, Wk, bk, Wv, bv);
    attn_kernel<<<BATCH * NQB, THREADS, SMEM_BYTES>>>(x, Wo, bo, gamma, y);
}